// round 9
// baseline (speedup 1.0000x reference)
#include <cuda_runtime.h>
#include <cstdint>
#include <math.h>

#define NST    512
#define NOBS   1024
#define NBATCH 64
#define TMAX   512

#define RANKS   8
#define ITILE   64
#define NB      4
#define NGRP    16
#define THREADS 512

// ---- shared memory layout (in floats) ----
#define OFF_AT   0                      // [512][64]        = 32768
#define OFF_P2   32768                  // [2][512][8] dup  = 8192
#define OFF_RED  40960                  // [4][2048]        = 8192
#define OFF_XR   49152                  // int [4][512]     = 2048
#define OFF_MAXB 51200                  // [2][8][4]        = 64
#define OFF_MUV  51264                  // [2][4]           = 8
#define OFF_WRED 51272                  // [8][4]           = 32
#define OFF_SRED 51304                  // [16]
#define OFF_TB   51320                  // int [4]
#define OFF_SS   51324                  // [2][4] scale ratios
#define OFF_MBAR 51332                  // 8 x u64 (8B aligned: 51332*4%8==0)
#define SMEM_FLOATS 51348
#define SMEM_BYTES  (SMEM_FLOATS * 4)

typedef unsigned long long ull;

// ---- device scratch ----
__device__ float g_At[NST * NST];      // [k][i] = P(i|k) = softmax_i(A[:,k])
__device__ float g_logEt[NOBS * NST];  // [m][i] = log_softmax_m(E[i,:])
__device__ float g_Ept[NOBS * NST];    // [m][i] = probability
__device__ float g_logpi[NST];

// ======================= helpers =======================

__device__ __forceinline__ float warpMax(float v) {
#pragma unroll
    for (int o = 16; o > 0; o >>= 1) v = fmaxf(v, __shfl_xor_sync(0xffffffffu, v, o));
    return v;
}
__device__ __forceinline__ float warpSum(float v) {
#pragma unroll
    for (int o = 16; o > 0; o >>= 1) v += __shfl_xor_sync(0xffffffffu, v, o);
    return v;
}
__device__ __forceinline__ float blockMax512(float v, float* sc) {
    float w = warpMax(v);
    int wid = threadIdx.x >> 5;
    if ((threadIdx.x & 31) == 0) sc[wid] = w;
    __syncthreads();
    if (threadIdx.x < 32) {
        float x = (threadIdx.x < 16) ? sc[threadIdx.x] : -INFINITY;
        x = warpMax(x);
        if (threadIdx.x == 0) sc[0] = x;
    }
    __syncthreads();
    float r = sc[0];
    __syncthreads();
    return r;
}
__device__ __forceinline__ float blockSum512(float v, float* sc) {
    float w = warpSum(v);
    int wid = threadIdx.x >> 5;
    if ((threadIdx.x & 31) == 0) sc[wid] = w;
    __syncthreads();
    if (threadIdx.x < 32) {
        float x = (threadIdx.x < 16) ? sc[threadIdx.x] : 0.0f;
        x = warpSum(x);
        if (threadIdx.x == 0) sc[0] = x;
    }
    __syncthreads();
    float r = sc[0];
    __syncthreads();
    return r;
}

__device__ __forceinline__ uint32_t smem_u32(const void* p) {
    return (uint32_t)__cvta_generic_to_shared(p);
}
__device__ __forceinline__ uint32_t mapa_u32(uint32_t a, uint32_t rank) {
    uint32_t d;
    asm("mapa.shared::cluster.u32 %0, %1, %2;" : "=r"(d) : "r"(a), "r"(rank));
    return d;
}
__device__ __forceinline__ void st_cluster_f32(uint32_t a, float v) {
    asm volatile("st.shared::cluster.f32 [%0], %1;" :: "r"(a), "f"(v) : "memory");
}
__device__ __forceinline__ void st_cluster_v4(uint32_t a, float4 v) {
    asm volatile("st.shared::cluster.v4.f32 [%0], {%1,%2,%3,%4};"
                 :: "r"(a), "f"(v.x), "f"(v.y), "f"(v.z), "f"(v.w) : "memory");
}
__device__ __forceinline__ void cluster_arrive() {
    asm volatile("barrier.cluster.arrive.aligned;" ::: "memory");
}
__device__ __forceinline__ void cluster_wait() {
    asm volatile("barrier.cluster.wait.aligned;" ::: "memory");
}

// ---- mbarrier ops ----
__device__ __forceinline__ void mbar_init(uint32_t a, uint32_t cnt) {
    asm volatile("mbarrier.init.shared.b64 [%0], %1;" :: "r"(a), "r"(cnt) : "memory");
}
__device__ __forceinline__ void mbar_arrive_peer(uint32_t a, uint32_t peer) {
    asm volatile(
        "{\n\t.reg .b32 ra;\n\t"
        "mapa.shared::cluster.u32 ra, %0, %1;\n\t"
        "mbarrier.arrive.release.cluster.shared::cluster.b64 _, [ra];\n\t}"
        :: "r"(a), "r"(peer) : "memory");
}
// CLUSTER-scope acquire: required to observe peer CTAs' st.shared::cluster data.
__device__ __forceinline__ void mbar_wait_parity(uint32_t a, uint32_t ph) {
    uint32_t done;
    asm volatile(
        "{\n\t.reg .pred p;\n\t"
        "mbarrier.try_wait.parity.acquire.cluster.shared::cta.b64 p, [%1], %2;\n\t"
        "selp.b32 %0, 1, 0, p;\n\t}"
        : "=r"(done) : "r"(a), "r"(ph) : "memory");
    if (!done) {
        asm volatile(
            "{\n\t.reg .pred P1;\n\t"
            "WL_%=:\n\t"
            "mbarrier.try_wait.parity.acquire.cluster.shared::cta.b64 P1, [%0], %1, 0x989680;\n\t"
            "@P1 bra.uni WD_%=;\n\t"
            "bra.uni WL_%=;\n\t"
            "WD_%=:\n\t}"
            :: "r"(a), "r"(ph) : "memory");
    }
}

// ---- packed f32x2 FMA ----
__device__ __forceinline__ void ffma2(ull& d, ull a, ull b) {
    asm("fma.rn.f32x2 %0, %1, %2, %0;" : "+l"(d) : "l"(a), "l"(b));
}
__device__ __forceinline__ void unpk(ull v, float& lo, float& hi) {
    uint32_t a, b;
    asm("mov.b64 {%0, %1}, %2;" : "=r"(a), "=r"(b) : "l"(v));
    lo = __uint_as_float(a); hi = __uint_as_float(b);
}

// ======================= prep kernels =======================

__global__ void k_logpi(const float* __restrict__ pi) {
    __shared__ float sc[16];
    int t = threadIdx.x;
    float v = pi[t];
    float m = blockMax512(v, sc);
    float s = blockSum512(__expf(v - m), sc);
    g_logpi[t] = v - m - __logf(s);
}

__global__ void k_prepA(const float* __restrict__ A) {
    __shared__ float sc[16];
    int k = blockIdx.x;
    int i = threadIdx.x;
    float a = A[i * NST + k];
    float m = blockMax512(a, sc);
    float e = __expf(a - m);
    float s = blockSum512(e, sc);
    g_At[k * NST + i] = e / s;
}

__global__ void k_prepE(const float* __restrict__ E) {
    __shared__ float sc[16];
    int i = blockIdx.x;
    int t = threadIdx.x;
    float a0 = E[i * NOBS + t];
    float a1 = E[i * NOBS + t + 512];
    float m = blockMax512(fmaxf(a0, a1), sc);
    float s = blockSum512(__expf(a0 - m) + __expf(a1 - m), sc);
    float lse = m + __logf(s);
    float l0 = a0 - lse, l1 = a1 - lse;
    g_logEt[t * NST + i] = l0;
    g_logEt[(t + 512) * NST + i] = l1;
    g_Ept[t * NST + i] = __expf(l0);
    g_Ept[(t + 512) * NST + i] = __expf(l1);
}

// ======================= main kernel =======================
// 16 clusters x 8 CTAs. Cluster g: batches [4g,4g+4); rank r: states [64r,64r+64).
// Per-source mbarriers (cluster-scope acquire waits); fully linear recurrence with
// ANCHORED shift: S_new = Qc/S_old, p = q*S_old/Qc, mu += log S_new.

__global__ void __launch_bounds__(THREADS, 1) __cluster_dims__(RANKS, 1, 1)
hmm_main(const int* __restrict__ x, const int* __restrict__ Tarr,
         float* __restrict__ out)
{
    extern __shared__ float sm[];
    float* At_s   = sm + OFF_AT;
    float* p2     = sm + OFF_P2;     // [2][512][8] duplicated pairs
    float* red    = sm + OFF_RED;
    int*   xr     = (int*)(sm + OFF_XR);
    float* maxbuf = sm + OFF_MAXB;   // [2][8][4] (linear q-maxes)
    float* muv    = sm + OFF_MUV;    // [2][4]
    float* wred   = sm + OFF_WRED;   // [8][4]
    float* sred   = sm + OFF_SRED;
    int*   Tb     = (int*)(sm + OFF_TB);
    float* sS     = sm + OFF_SS;     // [2][4] scale ratios S = exp(M_t - M_{t-1})
    const uint32_t mbar0 = smem_u32(sm + OFF_MBAR);

    const int tid  = threadIdx.x;
    const int rank = blockIdx.x & (RANKS - 1);
    const int grp  = blockIdx.x >> 3;
    const int wid  = tid >> 5;
    const int lane = tid & 31;

    // FMA mapping
    const int ksl = tid >> 4;          // 0..31
    const int igm = tid & 15;          // 0..15
    const int my_src = wid >> 1;       // source rank for this warp's k-chunk
    const bool need_wait = (my_src != rank);
    const uint32_t my_mbar = mbar0 + my_src * 8;

    // owner mapping (tid < 256)
    const int iv   = tid >> 6;
    const int igo  = (tid & 63) >> 2;
    const int myb  = tid & 3;
    const int i_loc  = igo * 4 + iv;
    const int i_glob = rank * ITILE + i_loc;
    const int poff2  = (rank * ITILE + i_loc) * 8 + myb * 2;
    const int rbase  = iv * 2048 + (tid & 63);

    // --- load A slice, observations, lengths
    for (int idx = tid; idx < NST * (ITILE / 4); idx += THREADS) {
        int k = idx >> 4, v = idx & 15;
        float4 val = *(const float4*)(&g_At[k * NST + rank * ITILE + v * 4]);
        *(float4*)(&At_s[k * ITILE + v * 4]) = val;
    }
    for (int idx = tid; idx < NB * TMAX; idx += THREADS) {
        int b = idx >> 9, tt = idx & (TMAX - 1);
        xr[b * TMAX + tt] = x[(grp * NB + b) * TMAX + tt];
    }
    if (tid < NB) Tb[tid] = Tarr[grp * NB + tid];
    if (tid < RANKS) mbar_init(mbar0 + tid * 8, 1);
    __syncthreads();
    cluster_arrive(); cluster_wait();   // mbarrier init visible cluster-wide

    // --- alpha0 (log domain, one-time) + per-warp per-b max
    float alpha0 = 0.0f;
    if (tid < 256) {
        int obs = xr[myb * TMAX + 0];
        alpha0 = g_logpi[i_glob] + g_logEt[obs * NST + i_glob];
        float m = alpha0;
        m = fmaxf(m, __shfl_xor_sync(0xffffffffu, m, 4));
        m = fmaxf(m, __shfl_xor_sync(0xffffffffu, m, 8));
        m = fmaxf(m, __shfl_xor_sync(0xffffffffu, m, 16));
        if (lane < 4) wred[wid * 4 + myb] = m;
    }
    __syncthreads();

    // --- exchange log-maxes exactly (one-time cluster barrier)
    if (tid < NB) {
        float lm = wred[tid];
#pragma unroll
        for (int w = 1; w < 8; w++) lm = fmaxf(lm, wred[w * 4 + tid]);
        maxbuf[32 + rank * NB + tid] = lm;
        uint32_t la = smem_u32(&maxbuf[32 + rank * NB + tid]);
        for (int r = 0; r < RANKS; r++)
            if (r != rank) st_cluster_f32(mapa_u32(la, r), lm);
    }
    cluster_arrive(); cluster_wait();

    const int Tlim = max(max(Tb[0], Tb[1]), max(Tb[2], Tb[3]));

    // --- p0 into buf1 (dup pairs); maxbuf[1] logs -> linear rel to m0; S=1
    float lin_init = 0.0f;
    {
        if (tid < 256) {
            float m0 = maxbuf[32 + myb];
#pragma unroll
            for (int r = 1; r < 8; r++) m0 = fmaxf(m0, maxbuf[32 + r * 4 + myb]);
            float pv = __expf(alpha0 - m0);
            *(float2*)(&p2[4096 + poff2]) = make_float2(pv, pv);
            if (tid < 4) { muv[4 + myb] = m0; sS[4 + myb] = 1.0f; }
        }
        if (tid < 32) {
            int b = tid & 3;
            float m0 = maxbuf[32 + b];
#pragma unroll
            for (int r = 1; r < 8; r++) m0 = fmaxf(m0, maxbuf[32 + r * 4 + b]);
            lin_init = __expf(maxbuf[32 + tid] - m0);
        }
    }
    __syncthreads();
    if (tid < 32) maxbuf[32 + tid] = lin_init;   // cluster-max == 1.0
    __syncthreads();

    // --- initial push of p0 chunks (warps 0-6), per-source arrive
    {
        const float* pbn2 = p2 + 4096;
        if (wid < 7) {
            int peer = wid + (wid >= rank);
            uint32_t lbase = smem_u32(&pbn2[rank * 512]);
            uint32_t rb0 = mapa_u32(lbase, peer);
#pragma unroll
            for (int j = 0; j < 4; j++) {
                float4 v = *(const float4*)(&pbn2[rank * 512 + (lane + 32 * j) * 4]);
                st_cluster_v4(rb0 + (lane + 32 * j) * 16, v);
            }
            __syncwarp();
            if (lane == 0) mbar_arrive_peer(mbar0 + rank * 8, peer);
        }
    }

    // ===================== time loop =====================
    for (int t = 1; t <= Tlim; t++) {
        const int buf = t & 1;
        const float* pb2 = p2 + buf * 4096;

        // emission-probability prefetch (input-only: issue BEFORE wait)
        float ep = 0.0f;
        if (tid < 256 && t < Tlim) {
            int obs = xr[myb * TMAX + t];
            ep = g_Ept[obs * NST + i_glob];
        }

        // wait only for MY source's chunk (own source: no wait)
        if (need_wait) mbar_wait_parity(my_mbar, (t - 1) & 1);

        // output: pb2 holds p(alpha_{t-1}); answer when t == T[b]
#pragma unroll
        for (int b = 0; b < NB; b++) {
            if (Tb[b] == t) {
                float part = pb2[tid * 8 + b * 2];   // tid == k
                float ws = warpSum(part);
                if (lane == 0) sred[wid] = ws;
                __syncthreads();
                if (tid == 0 && rank == 0) {
                    float s = 0.0f;
#pragma unroll
                    for (int w = 0; w < 16; w++) s += sred[w];
                    out[grp * NB + b] = muv[buf * 4 + b] + __logf(s);
                }
                __syncthreads();
            }
        }
        if (t == Tlim) break;

        // ---- FMA: tot[i,b] = sum_k At[k][i] * p[k][b]  (FFMA2, dup operands)
        {
            const float* Ab = At_s + igm * 4;
            const ulonglong2* Pb = (const ulonglong2*)pb2;
            ull a00 = 0, a01 = 0, a02 = 0, a03 = 0;
            ull a10 = 0, a11 = 0, a12 = 0, a13 = 0;
            const int k0 = ksl * 16;
#pragma unroll
            for (int kk = 0; kk < 16; kk++) {
                int k = k0 + kk;
                ulonglong2 a2 = *(const ulonglong2*)(Ab + k * ITILE);
                ulonglong2 q01 = Pb[2 * k];
                ulonglong2 q23 = Pb[2 * k + 1];
                ffma2(a00, a2.x, q01.x); ffma2(a01, a2.x, q01.y);
                ffma2(a02, a2.x, q23.x); ffma2(a03, a2.x, q23.y);
                ffma2(a10, a2.y, q01.x); ffma2(a11, a2.y, q01.y);
                ffma2(a12, a2.y, q23.x); ffma2(a13, a2.y, q23.y);
            }
            float l0, h0, l1, h1, l2, h2, l3, h3;
            unpk(a00, l0, h0); unpk(a01, l1, h1);
            unpk(a02, l2, h2); unpk(a03, l3, h3);
            *(float4*)(red + 0 * 2048 + tid * 4) = make_float4(l0, l1, l2, l3);
            *(float4*)(red + 1 * 2048 + tid * 4) = make_float4(h0, h1, h2, h3);
            unpk(a10, l0, h0); unpk(a11, l1, h1);
            unpk(a12, l2, h2); unpk(a13, l3, h3);
            *(float4*)(red + 2 * 2048 + tid * 4) = make_float4(l0, l1, l2, l3);
            *(float4*)(red + 3 * 2048 + tid * 4) = make_float4(h0, h1, h2, h3);
        }
        __syncthreads();

        // ---- phase B (linear, anchored): q = tot*ep; p = q*S_old/Qc; S_new = Qc/S_old
        if (tid < 256) {
            const float* rb = red + rbase;
            float t0 = 0.f, t1 = 0.f, t2 = 0.f, t3 = 0.f;
#pragma unroll
            for (int q8 = 0; q8 < 8; q8++) {
                t0 += rb[(4 * q8 + 0) * 64];
                t1 += rb[(4 * q8 + 1) * 64];
                t2 += rb[(4 * q8 + 2) * 64];
                t3 += rb[(4 * q8 + 3) * 64];
            }
            float tot = fmaxf((t0 + t1) + (t2 + t3), 1e-37f);

            // Qc = cluster max of previous q (arrived with pushes)
            float Qc = maxbuf[buf * 32 + myb];
#pragma unroll
            for (int r = 1; r < 8; r++)
                Qc = fmaxf(Qc, maxbuf[buf * 32 + r * 4 + myb]);
            float S_old = sS[buf * 4 + myb];
            float q = tot * ep;
            float pv = q * S_old * __frcp_rn(Qc);   // = q / S_new; M stays anchored

            float* pbn2 = p2 + (buf ^ 1) * 4096;
            *(float2*)(&pbn2[poff2]) = make_float2(pv, pv);

            if (tid < 4) {
                float S_new = Qc * __frcp_rn(S_old);
                sS[(buf ^ 1) * 4 + myb] = S_new;
                muv[(buf ^ 1) * 4 + myb] = muv[buf * 4 + myb] + __logf(S_new);
            }

            // per-warp linear max of q for next step's Qc
            float m = q;
            m = fmaxf(m, __shfl_xor_sync(0xffffffffu, m, 4));
            m = fmaxf(m, __shfl_xor_sync(0xffffffffu, m, 8));
            m = fmaxf(m, __shfl_xor_sync(0xffffffffu, m, 16));
            if (lane < 4) wred[wid * 4 + myb] = m;
        }
        __syncthreads();

        // ---- push p_next + q-maxes to peers; per-source arrive
        {
            const int bn = buf ^ 1;
            const float* pbn2 = p2 + bn * 4096;
            if (wid < 7) {
                int peer = wid + (wid >= rank);
                uint32_t lbase = smem_u32(&pbn2[rank * 512]);
                uint32_t rb0 = mapa_u32(lbase, peer);
#pragma unroll
                for (int j = 0; j < 4; j++) {
                    float4 v = *(const float4*)(&pbn2[rank * 512 + (lane + 32 * j) * 4]);
                    st_cluster_v4(rb0 + (lane + 32 * j) * 16, v);
                }
                if (lane < 4) {
                    float lm = wred[lane];
#pragma unroll
                    for (int w = 1; w < 8; w++) lm = fmaxf(lm, wred[w * 4 + lane]);
                    uint32_t ma = smem_u32(&maxbuf[bn * 32 + rank * 4 + lane]);
                    st_cluster_f32(mapa_u32(ma, peer), lm);
                }
                __syncwarp();
                if (lane == 0) mbar_arrive_peer(mbar0 + rank * 8, peer);
            } else if (wid == 7) {
                if (lane < 4) {
                    float lm = wred[lane];
#pragma unroll
                    for (int w = 1; w < 8; w++) lm = fmaxf(lm, wred[w * 4 + lane]);
                    maxbuf[bn * 32 + rank * 4 + lane] = lm;
                }
            }
        }
    }
}

// ======================= launch =======================

extern "C" void kernel_launch(void* const* d_in, const int* in_sizes, int n_in,
                              void* d_out, int out_size)
{
    const float* pi = (const float*)d_in[0];
    const float* A  = (const float*)d_in[1];
    const float* E  = (const float*)d_in[2];
    const int*   x  = (const int*)d_in[3];
    const int*   T  = (const int*)d_in[4];
    float* out = (float*)d_out;

    cudaFuncSetAttribute(hmm_main, cudaFuncAttributeMaxDynamicSharedMemorySize,
                         SMEM_BYTES);

    k_logpi<<<1, 512>>>(pi);
    k_prepA<<<NST, 512>>>(A);
    k_prepE<<<NST, 512>>>(E);
    hmm_main<<<NGRP * RANKS, THREADS, SMEM_BYTES>>>(x, T, out);
}

// round 10
// speedup vs baseline: 1.2584x; 1.2584x over previous
#include <cuda_runtime.h>
#include <cstdint>
#include <math.h>

#define NST    512
#define NOBS   1024
#define NBATCH 64
#define TMAX   512

#define RANKS   8
#define ITILE   64
#define NB      4
#define NGRP    16
#define THREADS 512

// ---- shared memory layout (in floats) ----
#define OFF_AT   0                      // [512][64]      = 32768
#define OFF_P    32768                  // [2][512][4]    = 4096
#define OFF_RED  36864                  // [4][2048]      = 8192
#define OFF_XR   45056                  // int [4][512]   = 2048
#define OFF_MAXB 47104                  // [2][8][4]      = 64 (log maxes)
#define OFF_MUV  47168                  // [2][4]
#define OFF_WRED 47176                  // [8][4]
#define OFF_SRED 47208                  // [16]
#define OFF_TB   47224                  // int [4]
#define OFF_MBAR 47228                  // 8 x u64 (47228*4 % 8 == 0)
#define SMEM_FLOATS 47244
#define SMEM_BYTES  (SMEM_FLOATS * 4)

typedef unsigned long long ull;

// ---- device scratch ----
__device__ float g_At[NST * NST];      // [k][i] = P(i|k) = softmax_i(A[:,k])
__device__ float g_logEt[NOBS * NST];  // [m][i] = log_softmax_m(E[i,:])
__device__ float g_logpi[NST];

// ======================= helpers =======================

__device__ __forceinline__ float warpMax(float v) {
#pragma unroll
    for (int o = 16; o > 0; o >>= 1) v = fmaxf(v, __shfl_xor_sync(0xffffffffu, v, o));
    return v;
}
__device__ __forceinline__ float warpSum(float v) {
#pragma unroll
    for (int o = 16; o > 0; o >>= 1) v += __shfl_xor_sync(0xffffffffu, v, o);
    return v;
}
__device__ __forceinline__ float blockMax512(float v, float* sc) {
    float w = warpMax(v);
    int wid = threadIdx.x >> 5;
    if ((threadIdx.x & 31) == 0) sc[wid] = w;
    __syncthreads();
    if (threadIdx.x < 32) {
        float x = (threadIdx.x < 16) ? sc[threadIdx.x] : -INFINITY;
        x = warpMax(x);
        if (threadIdx.x == 0) sc[0] = x;
    }
    __syncthreads();
    float r = sc[0];
    __syncthreads();
    return r;
}
__device__ __forceinline__ float blockSum512(float v, float* sc) {
    float w = warpSum(v);
    int wid = threadIdx.x >> 5;
    if ((threadIdx.x & 31) == 0) sc[wid] = w;
    __syncthreads();
    if (threadIdx.x < 32) {
        float x = (threadIdx.x < 16) ? sc[threadIdx.x] : 0.0f;
        x = warpSum(x);
        if (threadIdx.x == 0) sc[0] = x;
    }
    __syncthreads();
    float r = sc[0];
    __syncthreads();
    return r;
}

__device__ __forceinline__ uint32_t smem_u32(const void* p) {
    return (uint32_t)__cvta_generic_to_shared(p);
}
__device__ __forceinline__ uint32_t mapa_u32(uint32_t a, uint32_t rank) {
    uint32_t d;
    asm("mapa.shared::cluster.u32 %0, %1, %2;" : "=r"(d) : "r"(a), "r"(rank));
    return d;
}
__device__ __forceinline__ void st_cluster_f32(uint32_t a, float v) {
    asm volatile("st.shared::cluster.f32 [%0], %1;" :: "r"(a), "f"(v) : "memory");
}
__device__ __forceinline__ void st_cluster_v4(uint32_t a, float4 v) {
    asm volatile("st.shared::cluster.v4.f32 [%0], {%1,%2,%3,%4};"
                 :: "r"(a), "f"(v.x), "f"(v.y), "f"(v.z), "f"(v.w) : "memory");
}
__device__ __forceinline__ void cluster_arrive() {
    asm volatile("barrier.cluster.arrive.aligned;" ::: "memory");
}
__device__ __forceinline__ void cluster_wait() {
    asm volatile("barrier.cluster.wait.aligned;" ::: "memory");
}

// ---- mbarrier ops ----
__device__ __forceinline__ void mbar_init(uint32_t a, uint32_t cnt) {
    asm volatile("mbarrier.init.shared.b64 [%0], %1;" :: "r"(a), "r"(cnt) : "memory");
}
// Producer: RELEASE AT CLUSTER SCOPE — orders the preceding st.shared::cluster
// data stores ahead of the arrive in the cluster fabric (the R7 bug was the
// default .cta-scope release here).
__device__ __forceinline__ void mbar_arrive_peer(uint32_t a, uint32_t peer) {
    asm volatile(
        "{\n\t.reg .b32 ra;\n\t"
        "mapa.shared::cluster.u32 ra, %0, %1;\n\t"
        "mbarrier.arrive.release.cluster.shared::cluster.b64 _, [ra];\n\t}"
        :: "r"(a), "r"(peer) : "memory");
}
// Consumer: cheap CTA-scope acquire (R5-proven). Data lands in our own SMEM;
// once the locally-polled phase flips, ordering our own loads suffices.
__device__ __forceinline__ void mbar_wait_parity(uint32_t a, uint32_t ph) {
    uint32_t done;
    asm volatile(
        "{\n\t.reg .pred p;\n\t"
        "mbarrier.try_wait.parity.acquire.cta.shared::cta.b64 p, [%1], %2;\n\t"
        "selp.b32 %0, 1, 0, p;\n\t}"
        : "=r"(done) : "r"(a), "r"(ph) : "memory");
    if (!done) {
        asm volatile(
            "{\n\t.reg .pred P1;\n\t"
            "WL_%=:\n\t"
            "mbarrier.try_wait.parity.acquire.cta.shared::cta.b64 P1, [%0], %1, 0x989680;\n\t"
            "@P1 bra.uni WD_%=;\n\t"
            "bra.uni WL_%=;\n\t"
            "WD_%=:\n\t}"
            :: "r"(a), "r"(ph) : "memory");
    }
}

// ---- packed f32x2 FMA ----
__device__ __forceinline__ void ffma2(ull& d, ull a, ull b) {
    asm("fma.rn.f32x2 %0, %1, %2, %0;" : "+l"(d) : "l"(a), "l"(b));
}
__device__ __forceinline__ ull dup2(float p) {
    ull r; uint32_t u = __float_as_uint(p);
    asm("mov.b64 %0, {%1, %1};" : "=l"(r) : "r"(u));
    return r;
}
__device__ __forceinline__ void unpk(ull v, float& lo, float& hi) {
    uint32_t a, b;
    asm("mov.b64 {%0, %1}, %2;" : "=r"(a), "=r"(b) : "l"(v));
    lo = __uint_as_float(a); hi = __uint_as_float(b);
}

// ======================= prep kernels =======================

__global__ void k_logpi(const float* __restrict__ pi) {
    __shared__ float sc[16];
    int t = threadIdx.x;
    float v = pi[t];
    float m = blockMax512(v, sc);
    float s = blockSum512(__expf(v - m), sc);
    g_logpi[t] = v - m - __logf(s);
}

__global__ void k_prepA(const float* __restrict__ A) {
    __shared__ float sc[16];
    int k = blockIdx.x;
    int i = threadIdx.x;
    float a = A[i * NST + k];
    float m = blockMax512(a, sc);
    float e = __expf(a - m);
    float s = blockSum512(e, sc);
    g_At[k * NST + i] = e / s;
}

__global__ void k_prepE(const float* __restrict__ E) {
    __shared__ float sc[16];
    int i = blockIdx.x;
    int t = threadIdx.x;
    float a0 = E[i * NOBS + t];
    float a1 = E[i * NOBS + t + 512];
    float m = blockMax512(fmaxf(a0, a1), sc);
    float s = blockSum512(__expf(a0 - m) + __expf(a1 - m), sc);
    float lse = m + __logf(s);
    g_logEt[t * NST + i] = a0 - lse;
    g_logEt[(t + 512) * NST + i] = a1 - lse;
}

// ======================= main kernel =======================
// 16 clusters x 8 CTAs. Cluster g: batches [4g,4g+4); rank r: states [64r,64r+64).
// Per-source mbarriers (release.cluster producer / cta-acquire consumer);
// log-domain recurrence with one-step-stale max shift (race-tolerant).

__global__ void __launch_bounds__(THREADS, 1) __cluster_dims__(RANKS, 1, 1)
hmm_main(const int* __restrict__ x, const int* __restrict__ Tarr,
         float* __restrict__ out)
{
    extern __shared__ float sm[];
    float* At_s   = sm + OFF_AT;
    float* p_s    = sm + OFF_P;      // [2][512][4]
    float* red    = sm + OFF_RED;
    int*   xr     = (int*)(sm + OFF_XR);
    float* maxbuf = sm + OFF_MAXB;   // [2][8][4] log maxes of alpha
    float* muv    = sm + OFF_MUV;    // [2][4]
    float* wred   = sm + OFF_WRED;   // [8][4]
    float* sred   = sm + OFF_SRED;
    int*   Tb     = (int*)(sm + OFF_TB);
    const uint32_t mbar0 = smem_u32(sm + OFF_MBAR);

    const int tid  = threadIdx.x;
    const int rank = blockIdx.x & (RANKS - 1);
    const int grp  = blockIdx.x >> 3;
    const int wid  = tid >> 5;
    const int lane = tid & 31;

    // FMA mapping
    const int ksl = tid >> 4;          // 0..31
    const int igm = tid & 15;          // 0..15
    const int my_src = wid >> 1;       // source rank for this warp's k-chunk
    const bool need_wait = (my_src != rank);
    const uint32_t my_mbar = mbar0 + my_src * 8;

    // owner mapping (tid < 256)
    const int iv   = tid >> 6;
    const int igo  = (tid & 63) >> 2;
    const int myb  = tid & 3;
    const int i_loc  = igo * 4 + iv;
    const int i_glob = rank * ITILE + i_loc;
    const int poff   = rank * 256 + i_loc * 4 + myb;
    const int rbase  = iv * 2048 + (tid & 63);

    // --- load A slice, observations, lengths
    for (int idx = tid; idx < NST * (ITILE / 4); idx += THREADS) {
        int k = idx >> 4, v = idx & 15;
        float4 val = *(const float4*)(&g_At[k * NST + rank * ITILE + v * 4]);
        *(float4*)(&At_s[k * ITILE + v * 4]) = val;
    }
    for (int idx = tid; idx < NB * TMAX; idx += THREADS) {
        int b = idx >> 9, tt = idx & (TMAX - 1);
        xr[b * TMAX + tt] = x[(grp * NB + b) * TMAX + tt];
    }
    if (tid < NB) Tb[tid] = Tarr[grp * NB + tid];
    if (tid < RANKS) mbar_init(mbar0 + tid * 8, 1);
    __syncthreads();
    cluster_arrive(); cluster_wait();   // mbarrier init visible cluster-wide

    // --- alpha0 + per-warp per-b log maxes
    float alpha0 = 0.0f;
    if (tid < 256) {
        int obs = xr[myb * TMAX + 0];
        alpha0 = g_logpi[i_glob] + g_logEt[obs * NST + i_glob];
        float m = alpha0;
        m = fmaxf(m, __shfl_xor_sync(0xffffffffu, m, 4));
        m = fmaxf(m, __shfl_xor_sync(0xffffffffu, m, 8));
        m = fmaxf(m, __shfl_xor_sync(0xffffffffu, m, 16));
        if (lane < 4) wred[wid * 4 + myb] = m;
    }
    __syncthreads();

    // --- exchange alpha0 log-maxes exactly (one-time cluster barrier)
    if (tid < NB) {
        float lm = wred[tid];
#pragma unroll
        for (int w = 1; w < 8; w++) lm = fmaxf(lm, wred[w * 4 + tid]);
        maxbuf[32 + rank * NB + tid] = lm;
        uint32_t la = smem_u32(&maxbuf[32 + rank * NB + tid]);
        for (int r = 0; r < RANKS; r++)
            if (r != rank) st_cluster_f32(mapa_u32(la, r), lm);
    }
    cluster_arrive(); cluster_wait();

    const int Tlim = max(max(Tb[0], Tb[1]), max(Tb[2], Tb[3]));

    // --- p0 into buf1; mu_reg = m0 (exact max of alpha0)
    float mu_reg = 0.0f;
    if (tid < 256) {
        float m0 = maxbuf[32 + myb];
#pragma unroll
        for (int r = 1; r < 8; r++) m0 = fmaxf(m0, maxbuf[32 + r * 4 + myb]);
        mu_reg = m0;
        p_s[2048 + poff] = __expf(alpha0 - m0);
        if (tid < 4) muv[4 + myb] = m0;
    }
    __syncthreads();

    // --- initial push of p0 chunks (warps 0-6), per-source release.cluster arrive
    {
        const float* pbn = p_s + 2048;
        if (wid < 7) {
            int peer = wid + (wid >= rank);
            uint32_t lbase = smem_u32(&pbn[rank * 256]);
            uint32_t rb0 = mapa_u32(lbase, peer);
            float4 v0 = *(const float4*)(&pbn[rank * 256 + lane * 4]);
            float4 v1 = *(const float4*)(&pbn[rank * 256 + (lane + 32) * 4]);
            st_cluster_v4(rb0 + lane * 16, v0);
            st_cluster_v4(rb0 + (lane + 32) * 16, v1);
            __syncwarp();
            if (lane == 0) mbar_arrive_peer(mbar0 + rank * 8, peer);
        }
    }

    // ===================== time loop =====================
    for (int t = 1; t <= Tlim; t++) {
        const int buf = t & 1;
        const float* pb = p_s + buf * 2048;

        // emission log-prob prefetch (input-only: issue BEFORE the wait)
        float em = 0.0f;
        if (tid < 256 && t < Tlim) {
            int obs = xr[myb * TMAX + t];
            em = g_logEt[obs * NST + i_glob];
        }

        // wait only for MY source's chunk (own source: no wait)
        if (need_wait) mbar_wait_parity(my_mbar, (t - 1) & 1);

        // output: pb holds p(alpha_{t-1}); answer when t == T[b]
#pragma unroll
        for (int b = 0; b < NB; b++) {
            if (Tb[b] == t) {
                float part = pb[tid * NB + b];       // tid == k
                float ws = warpSum(part);
                if (lane == 0) sred[wid] = ws;
                __syncthreads();
                if (tid == 0 && rank == 0) {
                    float s = 0.0f;
#pragma unroll
                    for (int w = 0; w < 16; w++) s += sred[w];
                    out[grp * NB + b] = muv[buf * 4 + b] + __logf(s);
                }
                __syncthreads();
            }
        }
        if (t == Tlim) break;

        // ---- FMA: tot[i,b] = sum_k At[k][i] * p[k][b]  (FFMA2)
        {
            const float* Ab = At_s + igm * 4;
            const float4* Pb4 = (const float4*)pb;
            ull a00 = 0, a01 = 0, a02 = 0, a03 = 0;
            ull a10 = 0, a11 = 0, a12 = 0, a13 = 0;
            const int k0 = ksl * 16;
#pragma unroll
            for (int kk = 0; kk < 16; kk++) {
                int k = k0 + kk;
                ulonglong2 a2 = *(const ulonglong2*)(Ab + k * ITILE);
                float4 p4 = Pb4[k];
                ull p0 = dup2(p4.x), p1 = dup2(p4.y);
                ull p2v = dup2(p4.z), p3 = dup2(p4.w);
                ffma2(a00, a2.x, p0); ffma2(a01, a2.x, p1);
                ffma2(a02, a2.x, p2v); ffma2(a03, a2.x, p3);
                ffma2(a10, a2.y, p0); ffma2(a11, a2.y, p1);
                ffma2(a12, a2.y, p2v); ffma2(a13, a2.y, p3);
            }
            float l0, h0, l1, h1, l2, h2, l3, h3;
            unpk(a00, l0, h0); unpk(a01, l1, h1);
            unpk(a02, l2, h2); unpk(a03, l3, h3);
            *(float4*)(red + 0 * 2048 + tid * 4) = make_float4(l0, l1, l2, l3);
            *(float4*)(red + 1 * 2048 + tid * 4) = make_float4(h0, h1, h2, h3);
            unpk(a10, l0, h0); unpk(a11, l1, h1);
            unpk(a12, l2, h2); unpk(a13, l3, h3);
            *(float4*)(red + 2 * 2048 + tid * 4) = make_float4(l0, l1, l2, l3);
            *(float4*)(red + 3 * 2048 + tid * 4) = make_float4(h0, h1, h2, h3);
        }
        __syncthreads();

        // ---- phase B (log domain): alpha = log(tot)+mu+em; p = exp(alpha - mun)
        if (tid < 256) {
            const float* rb = red + rbase;
            float t0 = 0.f, t1 = 0.f, t2 = 0.f, t3 = 0.f;
#pragma unroll
            for (int q8 = 0; q8 < 8; q8++) {
                t0 += rb[(4 * q8 + 0) * 64];
                t1 += rb[(4 * q8 + 1) * 64];
                t2 += rb[(4 * q8 + 2) * 64];
                t3 += rb[(4 * q8 + 3) * 64];
            }
            float tot = fmaxf((t0 + t1) + (t2 + t3), 1e-37f);
            float alpha = __logf(tot) + mu_reg + em;

            // mun = max alpha_{t-1} (log maxes arrived with this step's pushes)
            float mun = maxbuf[buf * 32 + myb];
#pragma unroll
            for (int r = 1; r < 8; r++)
                mun = fmaxf(mun, maxbuf[buf * 32 + r * 4 + myb]);

            float* pbn = p_s + (buf ^ 1) * 2048;
            pbn[poff] = __expf(alpha - mun);
            mu_reg = mun;
            if (tid < 4) muv[(buf ^ 1) * 4 + myb] = mun;

            // per-warp log max of alpha for next step's mun
            float m = alpha;
            m = fmaxf(m, __shfl_xor_sync(0xffffffffu, m, 4));
            m = fmaxf(m, __shfl_xor_sync(0xffffffffu, m, 8));
            m = fmaxf(m, __shfl_xor_sync(0xffffffffu, m, 16));
            if (lane < 4) wred[wid * 4 + myb] = m;
        }
        __syncthreads();

        // ---- push p_next + log maxes to peers; release.cluster arrive
        {
            const int bn = buf ^ 1;
            const float* pbn = p_s + bn * 2048;
            if (wid < 7) {
                int peer = wid + (wid >= rank);
                uint32_t lbase = smem_u32(&pbn[rank * 256]);
                uint32_t rb0 = mapa_u32(lbase, peer);
                float4 v0 = *(const float4*)(&pbn[rank * 256 + lane * 4]);
                float4 v1 = *(const float4*)(&pbn[rank * 256 + (lane + 32) * 4]);
                st_cluster_v4(rb0 + lane * 16, v0);
                st_cluster_v4(rb0 + (lane + 32) * 16, v1);
                if (lane < 4) {
                    float lm = wred[lane];
#pragma unroll
                    for (int w = 1; w < 8; w++) lm = fmaxf(lm, wred[w * 4 + lane]);
                    uint32_t ma = smem_u32(&maxbuf[bn * 32 + rank * 4 + lane]);
                    st_cluster_f32(mapa_u32(ma, peer), lm);
                }
                __syncwarp();
                if (lane == 0) mbar_arrive_peer(mbar0 + rank * 8, peer);
            } else if (wid == 7) {
                if (lane < 4) {
                    float lm = wred[lane];
#pragma unroll
                    for (int w = 1; w < 8; w++) lm = fmaxf(lm, wred[w * 4 + lane]);
                    maxbuf[bn * 32 + rank * 4 + lane] = lm;
                }
            }
        }
    }
}

// ======================= launch =======================

extern "C" void kernel_launch(void* const* d_in, const int* in_sizes, int n_in,
                              void* d_out, int out_size)
{
    const float* pi = (const float*)d_in[0];
    const float* A  = (const float*)d_in[1];
    const float* E  = (const float*)d_in[2];
    const int*   x  = (const int*)d_in[3];
    const int*   T  = (const int*)d_in[4];
    float* out = (float*)d_out;

    cudaFuncSetAttribute(hmm_main, cudaFuncAttributeMaxDynamicSharedMemorySize,
                         SMEM_BYTES);

    k_logpi<<<1, 512>>>(pi);
    k_prepA<<<NST, 512>>>(A);
    k_prepE<<<NST, 512>>>(E);
    hmm_main<<<NGRP * RANKS, THREADS, SMEM_BYTES>>>(x, T, out);
}

// round 11
// speedup vs baseline: 1.2962x; 1.0301x over previous
#include <cuda_runtime.h>
#include <cstdint>
#include <math.h>

#define NST    512
#define NOBS   1024
#define NBATCH 64
#define TMAX   512

#define RANKS   8
#define ITILE   64
#define NB      4
#define NGRP    16
#define THREADS 512

// ---- shared memory layout (in floats) ----
#define OFF_AT   0                      // [512][64]        = 32768
#define OFF_P2   32768                  // [2][512][8] dup  = 8192
#define OFF_RED  40960                  // [4][2048]        = 8192
#define OFF_XR   49152                  // int [4][512]     = 2048
#define OFF_MAXB 51200                  // [2][8][4] log maxes = 64
#define OFF_MUV  51264                  // [2][4]
#define OFF_WRED 51272                  // [8][4]
#define OFF_SRED 51304                  // [16]
#define OFF_TB   51320                  // int [4]
#define OFF_MBAR 51324                  // 8 x u64 (51324*4 % 8 == 0)
#define SMEM_FLOATS 51340
#define SMEM_BYTES  (SMEM_FLOATS * 4)

typedef unsigned long long ull;

// ---- device scratch ----
__device__ float g_At[NST * NST];      // [k][i] = P(i|k) = softmax_i(A[:,k])
__device__ float g_logEt[NOBS * NST];  // [m][i] = log_softmax_m(E[i,:])
__device__ float g_logpi[NST];

// ======================= helpers =======================

__device__ __forceinline__ float warpMax(float v) {
#pragma unroll
    for (int o = 16; o > 0; o >>= 1) v = fmaxf(v, __shfl_xor_sync(0xffffffffu, v, o));
    return v;
}
__device__ __forceinline__ float warpSum(float v) {
#pragma unroll
    for (int o = 16; o > 0; o >>= 1) v += __shfl_xor_sync(0xffffffffu, v, o);
    return v;
}
__device__ __forceinline__ float blockMax512(float v, float* sc) {
    float w = warpMax(v);
    int wid = threadIdx.x >> 5;
    if ((threadIdx.x & 31) == 0) sc[wid] = w;
    __syncthreads();
    if (threadIdx.x < 32) {
        float x = (threadIdx.x < 16) ? sc[threadIdx.x] : -INFINITY;
        x = warpMax(x);
        if (threadIdx.x == 0) sc[0] = x;
    }
    __syncthreads();
    float r = sc[0];
    __syncthreads();
    return r;
}
__device__ __forceinline__ float blockSum512(float v, float* sc) {
    float w = warpSum(v);
    int wid = threadIdx.x >> 5;
    if ((threadIdx.x & 31) == 0) sc[wid] = w;
    __syncthreads();
    if (threadIdx.x < 32) {
        float x = (threadIdx.x < 16) ? sc[threadIdx.x] : 0.0f;
        x = warpSum(x);
        if (threadIdx.x == 0) sc[0] = x;
    }
    __syncthreads();
    float r = sc[0];
    __syncthreads();
    return r;
}

__device__ __forceinline__ uint32_t smem_u32(const void* p) {
    return (uint32_t)__cvta_generic_to_shared(p);
}
__device__ __forceinline__ uint32_t mapa_u32(uint32_t a, uint32_t rank) {
    uint32_t d;
    asm("mapa.shared::cluster.u32 %0, %1, %2;" : "=r"(d) : "r"(a), "r"(rank));
    return d;
}
__device__ __forceinline__ void st_cluster_f32(uint32_t a, float v) {
    asm volatile("st.shared::cluster.f32 [%0], %1;" :: "r"(a), "f"(v) : "memory");
}
__device__ __forceinline__ void st_cluster_v4(uint32_t a, float4 v) {
    asm volatile("st.shared::cluster.v4.f32 [%0], {%1,%2,%3,%4};"
                 :: "r"(a), "f"(v.x), "f"(v.y), "f"(v.z), "f"(v.w) : "memory");
}
__device__ __forceinline__ void cluster_arrive() {
    asm volatile("barrier.cluster.arrive.aligned;" ::: "memory");
}
__device__ __forceinline__ void cluster_wait() {
    asm volatile("barrier.cluster.wait.aligned;" ::: "memory");
}

// ---- mbarrier ops ----
__device__ __forceinline__ void mbar_init(uint32_t a, uint32_t cnt) {
    asm volatile("mbarrier.init.shared.b64 [%0], %1;" :: "r"(a), "r"(cnt) : "memory");
}
// Plain (cheap) arrive — R5-proven: data stores and the arrive travel the same
// DSMEM path to the same destination CTA; log-domain math tolerates metadata
// staleness regardless.
__device__ __forceinline__ void mbar_arrive_peer(uint32_t a, uint32_t peer) {
    asm volatile(
        "{\n\t.reg .b32 ra;\n\t"
        "mapa.shared::cluster.u32 ra, %0, %1;\n\t"
        "mbarrier.arrive.shared::cluster.b64 _, [ra];\n\t}"
        :: "r"(a), "r"(peer) : "memory");
}
// Consumer: cheap CTA-scope acquire (R5-proven).
__device__ __forceinline__ void mbar_wait_parity(uint32_t a, uint32_t ph) {
    uint32_t done;
    asm volatile(
        "{\n\t.reg .pred p;\n\t"
        "mbarrier.try_wait.parity.acquire.cta.shared::cta.b64 p, [%1], %2;\n\t"
        "selp.b32 %0, 1, 0, p;\n\t}"
        : "=r"(done) : "r"(a), "r"(ph) : "memory");
    if (!done) {
        asm volatile(
            "{\n\t.reg .pred P1;\n\t"
            "WL_%=:\n\t"
            "mbarrier.try_wait.parity.acquire.cta.shared::cta.b64 P1, [%0], %1, 0x989680;\n\t"
            "@P1 bra.uni WD_%=;\n\t"
            "bra.uni WL_%=;\n\t"
            "WD_%=:\n\t}"
            :: "r"(a), "r"(ph) : "memory");
    }
}

// ---- packed f32x2 FMA ----
__device__ __forceinline__ void ffma2(ull& d, ull a, ull b) {
    asm("fma.rn.f32x2 %0, %1, %2, %0;" : "+l"(d) : "l"(a), "l"(b));
}
__device__ __forceinline__ void unpk(ull v, float& lo, float& hi) {
    uint32_t a, b;
    asm("mov.b64 {%0, %1}, %2;" : "=r"(a), "=r"(b) : "l"(v));
    lo = __uint_as_float(a); hi = __uint_as_float(b);
}

// ======================= prep kernels =======================

__global__ void k_logpi(const float* __restrict__ pi) {
    __shared__ float sc[16];
    int t = threadIdx.x;
    float v = pi[t];
    float m = blockMax512(v, sc);
    float s = blockSum512(__expf(v - m), sc);
    g_logpi[t] = v - m - __logf(s);
}

__global__ void k_prepA(const float* __restrict__ A) {
    __shared__ float sc[16];
    int k = blockIdx.x;
    int i = threadIdx.x;
    float a = A[i * NST + k];
    float m = blockMax512(a, sc);
    float e = __expf(a - m);
    float s = blockSum512(e, sc);
    g_At[k * NST + i] = e / s;
}

__global__ void k_prepE(const float* __restrict__ E) {
    __shared__ float sc[16];
    int i = blockIdx.x;
    int t = threadIdx.x;
    float a0 = E[i * NOBS + t];
    float a1 = E[i * NOBS + t + 512];
    float m = blockMax512(fmaxf(a0, a1), sc);
    float s = blockSum512(__expf(a0 - m) + __expf(a1 - m), sc);
    float lse = m + __logf(s);
    g_logEt[t * NST + i] = a0 - lse;
    g_logEt[(t + 512) * NST + i] = a1 - lse;
}

// ======================= main kernel =======================
// 16 clusters x 8 CTAs. Cluster g: batches [4g,4g+4); rank r: states [64r,64r+64).
// Per-source mbarriers (plain arrives, cta-acquire waits); log-domain recurrence
// with one-step-stale max shift; p exchanged as duplicated {p,p} pairs so the
// FMA loop loads FFMA2-ready operands (no dup movs).

__global__ void __launch_bounds__(THREADS, 1) __cluster_dims__(RANKS, 1, 1)
hmm_main(const int* __restrict__ x, const int* __restrict__ Tarr,
         float* __restrict__ out)
{
    extern __shared__ float sm[];
    float* At_s   = sm + OFF_AT;
    float* p2     = sm + OFF_P2;     // [2][512][8] duplicated pairs
    float* red    = sm + OFF_RED;
    int*   xr     = (int*)(sm + OFF_XR);
    float* maxbuf = sm + OFF_MAXB;   // [2][8][4] log maxes of alpha
    float* muv    = sm + OFF_MUV;    // [2][4]
    float* wred   = sm + OFF_WRED;   // [8][4]
    float* sred   = sm + OFF_SRED;
    int*   Tb     = (int*)(sm + OFF_TB);
    const uint32_t mbar0 = smem_u32(sm + OFF_MBAR);

    const int tid  = threadIdx.x;
    const int rank = blockIdx.x & (RANKS - 1);
    const int grp  = blockIdx.x >> 3;
    const int wid  = tid >> 5;
    const int lane = tid & 31;

    // FMA mapping
    const int ksl = tid >> 4;          // 0..31
    const int igm = tid & 15;          // 0..15
    const int my_src = wid >> 1;       // source rank for this warp's k-chunk
    const bool need_wait = (my_src != rank);
    const uint32_t my_mbar = mbar0 + my_src * 8;

    // owner mapping (tid < 256)
    const int iv   = tid >> 6;
    const int igo  = (tid & 63) >> 2;
    const int myb  = tid & 3;
    const int i_loc  = igo * 4 + iv;
    const int i_glob = rank * ITILE + i_loc;
    const int poff2  = (rank * ITILE + i_loc) * 8 + myb * 2;
    const int rbase  = iv * 2048 + (tid & 63);

    // --- load A slice, observations, lengths
    for (int idx = tid; idx < NST * (ITILE / 4); idx += THREADS) {
        int k = idx >> 4, v = idx & 15;
        float4 val = *(const float4*)(&g_At[k * NST + rank * ITILE + v * 4]);
        *(float4*)(&At_s[k * ITILE + v * 4]) = val;
    }
    for (int idx = tid; idx < NB * TMAX; idx += THREADS) {
        int b = idx >> 9, tt = idx & (TMAX - 1);
        xr[b * TMAX + tt] = x[(grp * NB + b) * TMAX + tt];
    }
    if (tid < NB) Tb[tid] = Tarr[grp * NB + tid];
    if (tid < RANKS) mbar_init(mbar0 + tid * 8, 1);
    __syncthreads();
    cluster_arrive(); cluster_wait();   // mbarrier init visible cluster-wide

    // --- alpha0 + per-warp per-b log maxes
    float alpha0 = 0.0f;
    if (tid < 256) {
        int obs = xr[myb * TMAX + 0];
        alpha0 = g_logpi[i_glob] + g_logEt[obs * NST + i_glob];
        float m = alpha0;
        m = fmaxf(m, __shfl_xor_sync(0xffffffffu, m, 4));
        m = fmaxf(m, __shfl_xor_sync(0xffffffffu, m, 8));
        m = fmaxf(m, __shfl_xor_sync(0xffffffffu, m, 16));
        if (lane < 4) wred[wid * 4 + myb] = m;
    }
    __syncthreads();

    // --- exchange alpha0 log-maxes exactly (one-time cluster barrier)
    if (tid < NB) {
        float lm = wred[tid];
#pragma unroll
        for (int w = 1; w < 8; w++) lm = fmaxf(lm, wred[w * 4 + tid]);
        maxbuf[32 + rank * NB + tid] = lm;
        uint32_t la = smem_u32(&maxbuf[32 + rank * NB + tid]);
        for (int r = 0; r < RANKS; r++)
            if (r != rank) st_cluster_f32(mapa_u32(la, r), lm);
    }
    cluster_arrive(); cluster_wait();

    const int Tlim = max(max(Tb[0], Tb[1]), max(Tb[2], Tb[3]));

    // --- p0 into buf1 (dup pairs); mu_reg = m0 (exact max of alpha0)
    float mu_reg = 0.0f;
    if (tid < 256) {
        float m0 = maxbuf[32 + myb];
#pragma unroll
        for (int r = 1; r < 8; r++) m0 = fmaxf(m0, maxbuf[32 + r * 4 + myb]);
        mu_reg = m0;
        float pv = __expf(alpha0 - m0);
        *(float2*)(&p2[4096 + poff2]) = make_float2(pv, pv);
        if (tid < 4) muv[4 + myb] = m0;
    }
    __syncthreads();

    // --- initial push of p0 chunks (warps 0-6), per-source arrive
    {
        const float* pbn2 = p2 + 4096;
        if (wid < 7) {
            int peer = wid + (wid >= rank);
            uint32_t lbase = smem_u32(&pbn2[rank * 512]);
            uint32_t rb0 = mapa_u32(lbase, peer);
#pragma unroll
            for (int j = 0; j < 4; j++) {
                float4 v = *(const float4*)(&pbn2[rank * 512 + (lane + 32 * j) * 4]);
                st_cluster_v4(rb0 + (lane + 32 * j) * 16, v);
            }
            __syncwarp();
            if (lane == 0) mbar_arrive_peer(mbar0 + rank * 8, peer);
        }
    }

    // ===================== time loop =====================
    for (int t = 1; t <= Tlim; t++) {
        const int buf = t & 1;
        const float* pb2 = p2 + buf * 4096;

        // emission log-prob prefetch (input-only: issue BEFORE the wait)
        float em = 0.0f;
        if (tid < 256 && t < Tlim) {
            int obs = xr[myb * TMAX + t];
            em = g_logEt[obs * NST + i_glob];
        }

        // wait only for MY source's chunk (own source: no wait)
        if (need_wait) mbar_wait_parity(my_mbar, (t - 1) & 1);

        // output: pb2 holds p(alpha_{t-1}); answer when t == T[b]
#pragma unroll
        for (int b = 0; b < NB; b++) {
            if (Tb[b] == t) {
                float part = pb2[tid * 8 + b * 2];   // tid == k
                float ws = warpSum(part);
                if (lane == 0) sred[wid] = ws;
                __syncthreads();
                if (tid == 0 && rank == 0) {
                    float s = 0.0f;
#pragma unroll
                    for (int w = 0; w < 16; w++) s += sred[w];
                    out[grp * NB + b] = muv[buf * 4 + b] + __logf(s);
                }
                __syncthreads();
            }
        }
        if (t == Tlim) break;

        // ---- FMA: tot[i,b] = sum_k At[k][i] * p[k][b]  (FFMA2, dup operands)
        {
            const float* Ab = At_s + igm * 4;
            const ulonglong2* Pb = (const ulonglong2*)pb2;
            ull a00 = 0, a01 = 0, a02 = 0, a03 = 0;
            ull a10 = 0, a11 = 0, a12 = 0, a13 = 0;
            const int k0 = ksl * 16;
#pragma unroll
            for (int kk = 0; kk < 16; kk++) {
                int k = k0 + kk;
                ulonglong2 a2 = *(const ulonglong2*)(Ab + k * ITILE);
                ulonglong2 q01 = Pb[2 * k];
                ulonglong2 q23 = Pb[2 * k + 1];
                ffma2(a00, a2.x, q01.x); ffma2(a01, a2.x, q01.y);
                ffma2(a02, a2.x, q23.x); ffma2(a03, a2.x, q23.y);
                ffma2(a10, a2.y, q01.x); ffma2(a11, a2.y, q01.y);
                ffma2(a12, a2.y, q23.x); ffma2(a13, a2.y, q23.y);
            }
            float l0, h0, l1, h1, l2, h2, l3, h3;
            unpk(a00, l0, h0); unpk(a01, l1, h1);
            unpk(a02, l2, h2); unpk(a03, l3, h3);
            *(float4*)(red + 0 * 2048 + tid * 4) = make_float4(l0, l1, l2, l3);
            *(float4*)(red + 1 * 2048 + tid * 4) = make_float4(h0, h1, h2, h3);
            unpk(a10, l0, h0); unpk(a11, l1, h1);
            unpk(a12, l2, h2); unpk(a13, l3, h3);
            *(float4*)(red + 2 * 2048 + tid * 4) = make_float4(l0, l1, l2, l3);
            *(float4*)(red + 3 * 2048 + tid * 4) = make_float4(h0, h1, h2, h3);
        }
        __syncthreads();

        // ---- phase B (log domain): alpha = log(tot)+mu+em; p = exp(alpha - mun)
        if (tid < 256) {
            const float* rb = red + rbase;
            float t0 = 0.f, t1 = 0.f, t2 = 0.f, t3 = 0.f;
#pragma unroll
            for (int q8 = 0; q8 < 8; q8++) {
                t0 += rb[(4 * q8 + 0) * 64];
                t1 += rb[(4 * q8 + 1) * 64];
                t2 += rb[(4 * q8 + 2) * 64];
                t3 += rb[(4 * q8 + 3) * 64];
            }
            float tot = fmaxf((t0 + t1) + (t2 + t3), 1e-37f);
            float alpha = __logf(tot) + mu_reg + em;

            // mun = max alpha_{t-1} (log maxes arrived with this step's pushes)
            float mun = maxbuf[buf * 32 + myb];
#pragma unroll
            for (int r = 1; r < 8; r++)
                mun = fmaxf(mun, maxbuf[buf * 32 + r * 4 + myb]);

            float pv = __expf(alpha - mun);
            float* pbn2 = p2 + (buf ^ 1) * 4096;
            *(float2*)(&pbn2[poff2]) = make_float2(pv, pv);
            mu_reg = mun;
            if (tid < 4) muv[(buf ^ 1) * 4 + myb] = mun;

            // per-warp log max of alpha for next step's mun
            float m = alpha;
            m = fmaxf(m, __shfl_xor_sync(0xffffffffu, m, 4));
            m = fmaxf(m, __shfl_xor_sync(0xffffffffu, m, 8));
            m = fmaxf(m, __shfl_xor_sync(0xffffffffu, m, 16));
            if (lane < 4) wred[wid * 4 + myb] = m;
        }
        __syncthreads();

        // ---- push p_next + log maxes to peers; plain arrive
        {
            const int bn = buf ^ 1;
            const float* pbn2 = p2 + bn * 4096;
            if (wid < 7) {
                int peer = wid + (wid >= rank);
                uint32_t lbase = smem_u32(&pbn2[rank * 512]);
                uint32_t rb0 = mapa_u32(lbase, peer);
#pragma unroll
                for (int j = 0; j < 4; j++) {
                    float4 v = *(const float4*)(&pbn2[rank * 512 + (lane + 32 * j) * 4]);
                    st_cluster_v4(rb0 + (lane + 32 * j) * 16, v);
                }
                if (lane < 4) {
                    float lm = wred[lane];
#pragma unroll
                    for (int w = 1; w < 8; w++) lm = fmaxf(lm, wred[w * 4 + lane]);
                    uint32_t ma = smem_u32(&maxbuf[bn * 32 + rank * 4 + lane]);
                    st_cluster_f32(mapa_u32(ma, peer), lm);
                }
                __syncwarp();
                if (lane == 0) mbar_arrive_peer(mbar0 + rank * 8, peer);
            } else if (wid == 7) {
                if (lane < 4) {
                    float lm = wred[lane];
#pragma unroll
                    for (int w = 1; w < 8; w++) lm = fmaxf(lm, wred[w * 4 + lane]);
                    maxbuf[bn * 32 + rank * 4 + lane] = lm;
                }
            }
        }
    }
}

// ======================= launch =======================

extern "C" void kernel_launch(void* const* d_in, const int* in_sizes, int n_in,
                              void* d_out, int out_size)
{
    const float* pi = (const float*)d_in[0];
    const float* A  = (const float*)d_in[1];
    const float* E  = (const float*)d_in[2];
    const int*   x  = (const int*)d_in[3];
    const int*   T  = (const int*)d_in[4];
    float* out = (float*)d_out;

    cudaFuncSetAttribute(hmm_main, cudaFuncAttributeMaxDynamicSharedMemorySize,
                         SMEM_BYTES);

    k_logpi<<<1, 512>>>(pi);
    k_prepA<<<NST, 512>>>(A);
    k_prepE<<<NST, 512>>>(E);
    hmm_main<<<NGRP * RANKS, THREADS, SMEM_BYTES>>>(x, T, out);
}

// round 15
// speedup vs baseline: 1.5452x; 1.1921x over previous
#include <cuda_runtime.h>
#include <cstdint>
#include <math.h>

#define NST    512
#define NOBS   1024
#define NBATCH 64
#define TMAX   512

#define RANKS   8
#define ITILE   64
#define NB      4
#define NGRP    16
#define THREADS 512

// ---- shared memory layout (in floats) ----
#define OFF_AT   0                      // [512][64]      = 32768
#define OFF_P    32768                  // [2][512][4]    = 4096
#define OFF_RED  36864                  // [2][4][2048]   = 16384 (double buffered)
#define OFF_XR   53248                  // int [4][512]   = 2048
#define OFF_MAXB 55296                  // [2][8][4] log maxes = 64
#define OFF_MUV  55360                  // [2][4]
#define OFF_WRED 55368                  // [8][4]
#define OFF_SRED 55400                  // [16]
#define OFF_TB   55416                  // int [4]
#define OFF_MBAR 55420                  // 1 x u64 (55420*4 % 8 == 0)
#define SMEM_FLOATS 55424
#define SMEM_BYTES  (SMEM_FLOATS * 4)

typedef unsigned long long ull;

// ---- device scratch ----
__device__ float g_At[NST * NST];      // [k][i] = P(i|k) = softmax_i(A[:,k])
__device__ float g_logEt[NOBS * NST];  // [m][i] = log_softmax_m(E[i,:])
__device__ float g_logpi[NST];

// ======================= helpers =======================

__device__ __forceinline__ float warpMax(float v) {
#pragma unroll
    for (int o = 16; o > 0; o >>= 1) v = fmaxf(v, __shfl_xor_sync(0xffffffffu, v, o));
    return v;
}
__device__ __forceinline__ float warpSum(float v) {
#pragma unroll
    for (int o = 16; o > 0; o >>= 1) v += __shfl_xor_sync(0xffffffffu, v, o);
    return v;
}
__device__ __forceinline__ float blockMax512(float v, float* sc) {
    float w = warpMax(v);
    int wid = threadIdx.x >> 5;
    if ((threadIdx.x & 31) == 0) sc[wid] = w;
    __syncthreads();
    if (threadIdx.x < 32) {
        float x = (threadIdx.x < 16) ? sc[threadIdx.x] : -INFINITY;
        x = warpMax(x);
        if (threadIdx.x == 0) sc[0] = x;
    }
    __syncthreads();
    float r = sc[0];
    __syncthreads();
    return r;
}
__device__ __forceinline__ float blockSum512(float v, float* sc) {
    float w = warpSum(v);
    int wid = threadIdx.x >> 5;
    if ((threadIdx.x & 31) == 0) sc[wid] = w;
    __syncthreads();
    if (threadIdx.x < 32) {
        float x = (threadIdx.x < 16) ? sc[threadIdx.x] : 0.0f;
        x = warpSum(x);
        if (threadIdx.x == 0) sc[0] = x;
    }
    __syncthreads();
    float r = sc[0];
    __syncthreads();
    return r;
}

__device__ __forceinline__ uint32_t smem_u32(const void* p) {
    return (uint32_t)__cvta_generic_to_shared(p);
}
__device__ __forceinline__ uint32_t mapa_u32(uint32_t a, uint32_t rank) {
    uint32_t d;
    asm("mapa.shared::cluster.u32 %0, %1, %2;" : "=r"(d) : "r"(a), "r"(rank));
    return d;
}
__device__ __forceinline__ void st_cluster_f32(uint32_t a, float v) {
    asm volatile("st.shared::cluster.f32 [%0], %1;" :: "r"(a), "f"(v) : "memory");
}
__device__ __forceinline__ void st_cluster_v4(uint32_t a, float4 v) {
    asm volatile("st.shared::cluster.v4.f32 [%0], {%1,%2,%3,%4};"
                 :: "r"(a), "f"(v.x), "f"(v.y), "f"(v.z), "f"(v.w) : "memory");
}
__device__ __forceinline__ void cluster_arrive() {
    asm volatile("barrier.cluster.arrive.aligned;" ::: "memory");
}
__device__ __forceinline__ void cluster_wait() {
    asm volatile("barrier.cluster.wait.aligned;" ::: "memory");
}
__device__ __forceinline__ void bar_arrive_named(int id, int cnt) {
    asm volatile("bar.arrive %0, %1;" :: "r"(id), "r"(cnt) : "memory");
}
__device__ __forceinline__ void bar_sync_named(int id, int cnt) {
    asm volatile("bar.sync %0, %1;" :: "r"(id), "r"(cnt) : "memory");
}

// ---- mbarrier ops (R5-proven protocol) ----
__device__ __forceinline__ void mbar_init(uint32_t a, uint32_t cnt) {
    asm volatile("mbarrier.init.shared.b64 [%0], %1;" :: "r"(a), "r"(cnt) : "memory");
}
__device__ __forceinline__ void mbar_arrive_local(uint32_t a) {
    asm volatile("mbarrier.arrive.shared.b64 _, [%0];" :: "r"(a) : "memory");
}
__device__ __forceinline__ void mbar_arrive_peer(uint32_t a, uint32_t peer) {
    asm volatile(
        "{\n\t.reg .b32 ra;\n\t"
        "mapa.shared::cluster.u32 ra, %0, %1;\n\t"
        "mbarrier.arrive.shared::cluster.b64 _, [ra];\n\t}"
        :: "r"(a), "r"(peer) : "memory");
}
__device__ __forceinline__ void mbar_wait_parity(uint32_t a, uint32_t ph) {
    uint32_t done;
    asm volatile(
        "{\n\t.reg .pred p;\n\t"
        "mbarrier.try_wait.parity.acquire.cta.shared::cta.b64 p, [%1], %2;\n\t"
        "selp.b32 %0, 1, 0, p;\n\t}"
        : "=r"(done) : "r"(a), "r"(ph) : "memory");
    if (!done) {
        asm volatile(
            "{\n\t.reg .pred P1;\n\t"
            "WL_%=:\n\t"
            "mbarrier.try_wait.parity.acquire.cta.shared::cta.b64 P1, [%0], %1, 0x989680;\n\t"
            "@P1 bra.uni WD_%=;\n\t"
            "bra.uni WL_%=;\n\t"
            "WD_%=:\n\t}"
            :: "r"(a), "r"(ph) : "memory");
    }
}

// ---- packed f32x2 FMA ----
__device__ __forceinline__ void ffma2(ull& d, ull a, ull b) {
    asm("fma.rn.f32x2 %0, %1, %2, %0;" : "+l"(d) : "l"(a), "l"(b));
}
__device__ __forceinline__ ull dup2(float p) {
    ull r; uint32_t u = __float_as_uint(p);
    asm("mov.b64 %0, {%1, %1};" : "=l"(r) : "r"(u));
    return r;
}
__device__ __forceinline__ void unpk(ull v, float& lo, float& hi) {
    uint32_t a, b;
    asm("mov.b64 {%0, %1}, %2;" : "=r"(a), "=r"(b) : "l"(v));
    lo = __uint_as_float(a); hi = __uint_as_float(b);
}

// ======================= prep kernels =======================

__global__ void k_logpi(const float* __restrict__ pi) {
    __shared__ float sc[16];
    int t = threadIdx.x;
    float v = pi[t];
    float m = blockMax512(v, sc);
    float s = blockSum512(__expf(v - m), sc);
    g_logpi[t] = v - m - __logf(s);
}

__global__ void k_prepA(const float* __restrict__ A) {
    __shared__ float sc[16];
    int k = blockIdx.x;
    int i = threadIdx.x;
    float a = A[i * NST + k];
    float m = blockMax512(a, sc);
    float e = __expf(a - m);
    float s = blockSum512(e, sc);
    g_At[k * NST + i] = e / s;
}

__global__ void k_prepE(const float* __restrict__ E) {
    __shared__ float sc[16];
    int i = blockIdx.x;
    int t = threadIdx.x;
    float a0 = E[i * NOBS + t];
    float a1 = E[i * NOBS + t + 512];
    float m = blockMax512(fmaxf(a0, a1), sc);
    float s = blockSum512(__expf(a0 - m) + __expf(a1 - m), sc);
    float lse = m + __logf(s);
    g_logEt[t * NST + i] = a0 - lse;
    g_logEt[(t + 512) * NST + i] = a1 - lse;
}

// ======================= main kernel =======================
// 16 clusters x 8 CTAs. Cluster g: batches [4g,4g+4); rank r: states [64r,64r+64).
// R5 protocol (single mbarrier count=8) + warp-specialized tail:
//   warps 0-7: phaseB -> bar.arrive(1) -> maxes -> bar2 -> warp0 distributes maxes
//   warps 9-15: bar.sync(1) -> push p-chunk -> mbar arrive on peer
//   warp 8:     bar.sync(1) -> local mbar arrive
// red is double buffered so no trailing __syncthreads is needed.

__global__ void __launch_bounds__(THREADS, 1) __cluster_dims__(RANKS, 1, 1)
hmm_main(const int* __restrict__ x, const int* __restrict__ Tarr,
         float* __restrict__ out)
{
    extern __shared__ float sm[];
    float* At_s   = sm + OFF_AT;
    float* p_s    = sm + OFF_P;      // [2][512][4]
    float* red    = sm + OFF_RED;    // [2][4][2048]
    int*   xr     = (int*)(sm + OFF_XR);
    float* maxbuf = sm + OFF_MAXB;   // [2][8][4] log maxes of alpha
    float* muv    = sm + OFF_MUV;    // [2][4]
    float* wred   = sm + OFF_WRED;   // [8][4]
    float* sred   = sm + OFF_SRED;
    int*   Tb     = (int*)(sm + OFF_TB);
    const uint32_t mbar = smem_u32(sm + OFF_MBAR);

    const int tid  = threadIdx.x;
    const int rank = blockIdx.x & (RANKS - 1);
    const int grp  = blockIdx.x >> 3;
    const int wid  = tid >> 5;
    const int lane = tid & 31;

    // FMA mapping
    const int ksl = tid >> 4;          // 0..31
    const int igm = tid & 15;          // 0..15

    // owner mapping (tid < 256)
    const int iv   = tid >> 6;
    const int igo  = (tid & 63) >> 2;
    const int myb  = tid & 3;
    const int i_loc  = igo * 4 + iv;
    const int i_glob = rank * ITILE + i_loc;
    const int poff   = rank * 256 + i_loc * 4 + myb;
    const int rbase  = iv * 2048 + (tid & 63);

    // --- load A slice, observations, lengths
    for (int idx = tid; idx < NST * (ITILE / 4); idx += THREADS) {
        int k = idx >> 4, v = idx & 15;
        float4 val = *(const float4*)(&g_At[k * NST + rank * ITILE + v * 4]);
        *(float4*)(&At_s[k * ITILE + v * 4]) = val;
    }
    for (int idx = tid; idx < NB * TMAX; idx += THREADS) {
        int b = idx >> 9, tt = idx & (TMAX - 1);
        xr[b * TMAX + tt] = x[(grp * NB + b) * TMAX + tt];
    }
    if (tid < NB) Tb[tid] = Tarr[grp * NB + tid];
    if (tid == 0) mbar_init(mbar, 8);
    __syncthreads();
    cluster_arrive(); cluster_wait();   // mbarrier init visible cluster-wide

    // --- alpha0 + per-warp per-b log maxes
    float alpha0 = 0.0f;
    if (tid < 256) {
        int obs = xr[myb * TMAX + 0];
        alpha0 = g_logpi[i_glob] + g_logEt[obs * NST + i_glob];
        float m = alpha0;
        m = fmaxf(m, __shfl_xor_sync(0xffffffffu, m, 4));
        m = fmaxf(m, __shfl_xor_sync(0xffffffffu, m, 8));
        m = fmaxf(m, __shfl_xor_sync(0xffffffffu, m, 16));
        if (lane < 4) wred[wid * 4 + myb] = m;
    }
    __syncthreads();

    // --- exchange alpha0 log-maxes exactly (one-time cluster barrier)
    if (tid < NB) {
        float lm = wred[tid];
#pragma unroll
        for (int w = 1; w < 8; w++) lm = fmaxf(lm, wred[w * 4 + tid]);
        maxbuf[32 + rank * NB + tid] = lm;
        uint32_t la = smem_u32(&maxbuf[32 + rank * NB + tid]);
        for (int r = 0; r < RANKS; r++)
            if (r != rank) st_cluster_f32(mapa_u32(la, r), lm);
    }
    cluster_arrive(); cluster_wait();

    const int Tlim = max(max(Tb[0], Tb[1]), max(Tb[2], Tb[3]));

    // --- p0 into buf1; mu_reg = m0 (exact max of alpha0)
    float mu_reg = 0.0f;
    if (tid < 256) {
        float m0 = maxbuf[32 + myb];
#pragma unroll
        for (int r = 1; r < 8; r++) m0 = fmaxf(m0, maxbuf[32 + r * 4 + myb]);
        mu_reg = m0;
        p_s[2048 + poff] = __expf(alpha0 - m0);
        if (tid < 4) muv[4 + myb] = m0;
    }
    __syncthreads();

    // --- initial push of p0 chunks (warps 0-6), warp 7 local arrive
    {
        const float* pbn = p_s + 2048;
        if (wid < 7) {
            int peer = wid + (wid >= rank);
            uint32_t lbase = smem_u32(&pbn[rank * 256]);
            uint32_t rb0 = mapa_u32(lbase, peer);
            float4 v0 = *(const float4*)(&pbn[rank * 256 + lane * 4]);
            float4 v1 = *(const float4*)(&pbn[rank * 256 + (lane + 32) * 4]);
            st_cluster_v4(rb0 + lane * 16, v0);
            st_cluster_v4(rb0 + (lane + 32) * 16, v1);
            __syncwarp();
            if (lane == 0) mbar_arrive_peer(mbar, peer);
        } else if (wid == 7) {
            __syncwarp();
            if (lane == 0) mbar_arrive_local(mbar);
        }
    }

    // ===================== time loop =====================
    for (int t = 1; t <= Tlim; t++) {
        const int buf = t & 1;
        const float* pb = p_s + buf * 2048;
        float* redb = red + buf * 8192;
        const int bn = buf ^ 1;

        // emission log-prob prefetch (input-only: issue BEFORE the wait)
        float em = 0.0f;
        if (tid < 256 && t < Tlim) {
            int obs = xr[myb * TMAX + t];
            em = g_logEt[obs * NST + i_glob];
        }

        // wait for all 8 chunks of this step
        mbar_wait_parity(mbar, (t - 1) & 1);

        // output: pb holds p(alpha_{t-1}); answer when t == T[b]
#pragma unroll
        for (int b = 0; b < NB; b++) {
            if (Tb[b] == t) {
                float part = pb[tid * NB + b];       // tid == k
                float ws = warpSum(part);
                if (lane == 0) sred[wid] = ws;
                __syncthreads();
                if (tid == 0 && rank == 0) {
                    float s = 0.0f;
#pragma unroll
                    for (int w = 0; w < 16; w++) s += sred[w];
                    out[grp * NB + b] = muv[buf * 4 + b] + __logf(s);
                }
                __syncthreads();
            }
        }
        if (t == Tlim) break;

        // ---- FMA: tot[i,b] = sum_k At[k][i] * p[k][b]  (FFMA2)
        {
            const float* Ab = At_s + igm * 4;
            const float4* Pb4 = (const float4*)pb;
            ull a00 = 0, a01 = 0, a02 = 0, a03 = 0;
            ull a10 = 0, a11 = 0, a12 = 0, a13 = 0;
            const int k0 = ksl * 16;
#pragma unroll
            for (int kk = 0; kk < 16; kk++) {
                int k = k0 + kk;
                ulonglong2 a2 = *(const ulonglong2*)(Ab + k * ITILE);
                float4 p4 = Pb4[k];
                ull p0 = dup2(p4.x), p1 = dup2(p4.y);
                ull p2v = dup2(p4.z), p3 = dup2(p4.w);
                ffma2(a00, a2.x, p0); ffma2(a01, a2.x, p1);
                ffma2(a02, a2.x, p2v); ffma2(a03, a2.x, p3);
                ffma2(a10, a2.y, p0); ffma2(a11, a2.y, p1);
                ffma2(a12, a2.y, p2v); ffma2(a13, a2.y, p3);
            }
            float l0, h0, l1, h1, l2, h2, l3, h3;
            unpk(a00, l0, h0); unpk(a01, l1, h1);
            unpk(a02, l2, h2); unpk(a03, l3, h3);
            *(float4*)(redb + 0 * 2048 + tid * 4) = make_float4(l0, l1, l2, l3);
            *(float4*)(redb + 1 * 2048 + tid * 4) = make_float4(h0, h1, h2, h3);
            unpk(a10, l0, h0); unpk(a11, l1, h1);
            unpk(a12, l2, h2); unpk(a13, l3, h3);
            *(float4*)(redb + 2 * 2048 + tid * 4) = make_float4(l0, l1, l2, l3);
            *(float4*)(redb + 3 * 2048 + tid * 4) = make_float4(h0, h1, h2, h3);
        }
        __syncthreads();

        // ---- warp-specialized tail ----
        if (tid < 256) {
            // phase B (log domain): alpha = log(tot)+mu+em; p = exp(alpha - mun)
            const float* rb = redb + rbase;
            float t0 = 0.f, t1 = 0.f, t2 = 0.f, t3 = 0.f;
#pragma unroll
            for (int q8 = 0; q8 < 8; q8++) {
                t0 += rb[(4 * q8 + 0) * 64];
                t1 += rb[(4 * q8 + 1) * 64];
                t2 += rb[(4 * q8 + 2) * 64];
                t3 += rb[(4 * q8 + 3) * 64];
            }
            float tot = fmaxf((t0 + t1) + (t2 + t3), 1e-37f);
            float alpha = __logf(tot) + mu_reg + em;

            // mun = max alpha_{t-1} (arrived during previous step; stale-tolerant)
            float mun = maxbuf[buf * 32 + myb];
#pragma unroll
            for (int r = 1; r < 8; r++)
                mun = fmaxf(mun, maxbuf[buf * 32 + r * 4 + myb]);

            float* pbn = p_s + bn * 2048;
            pbn[poff] = __expf(alpha - mun);
            mu_reg = mun;
            if (tid < 4) muv[bn * 4 + myb] = mun;

            // release pushers: p stores for next step are done
            bar_arrive_named(1, 512);

            // per-warp log max of alpha (off critical path)
            float m = alpha;
            m = fmaxf(m, __shfl_xor_sync(0xffffffffu, m, 4));
            m = fmaxf(m, __shfl_xor_sync(0xffffffffu, m, 8));
            m = fmaxf(m, __shfl_xor_sync(0xffffffffu, m, 16));
            if (lane < 4) wred[wid * 4 + myb] = m;
            bar_sync_named(2, 256);

            // warp 0 distributes the 4 final maxes to all 8 ranks (unsync'd,
            // tolerated-stale metadata)
            if (wid == 0) {
                float fm = -INFINITY;
                if (lane < 4) {
                    fm = wred[lane];
#pragma unroll
                    for (int w = 1; w < 8; w++) fm = fmaxf(fm, wred[w * 4 + lane]);
                }
                float v = __shfl_sync(0xffffffffu, fm, lane & 3);
                int peer = lane >> 2;
                int slot = bn * 32 + rank * 4 + (lane & 3);
                if (peer == rank) {
                    maxbuf[slot] = v;
                } else {
                    st_cluster_f32(mapa_u32(smem_u32(&maxbuf[slot]), peer), v);
                }
            }
        } else {
            bar_sync_named(1, 512);
            const float* pbn = p_s + bn * 2048;
            if (wid >= 9) {
                int pw = wid - 9;                    // 0..6
                int peer = pw + (pw >= rank);
                uint32_t lbase = smem_u32(&pbn[rank * 256]);
                uint32_t rb0 = mapa_u32(lbase, peer);
                float4 v0 = *(const float4*)(&pbn[rank * 256 + lane * 4]);
                float4 v1 = *(const float4*)(&pbn[rank * 256 + (lane + 32) * 4]);
                st_cluster_v4(rb0 + lane * 16, v0);
                st_cluster_v4(rb0 + (lane + 32) * 16, v1);
                __syncwarp();
                if (lane == 0) mbar_arrive_peer(mbar, peer);
            } else {  // wid == 8: local arrive (covers local p visibility via bar 1)
                __syncwarp();
                if (lane == 0) mbar_arrive_local(mbar);
            }
        }
        // no trailing __syncthreads: red is double buffered; next-step reads of
        // pbn are gated by the mbarrier (local chunk via warp 8's post-bar1 arrive).
    }
}

// ======================= launch =======================

extern "C" void kernel_launch(void* const* d_in, const int* in_sizes, int n_in,
                              void* d_out, int out_size)
{
    const float* pi = (const float*)d_in[0];
    const float* A  = (const float*)d_in[1];
    const float* E  = (const float*)d_in[2];
    const int*   x  = (const int*)d_in[3];
    const int*   T  = (const int*)d_in[4];
    float* out = (float*)d_out;

    cudaFuncSetAttribute(hmm_main, cudaFuncAttributeMaxDynamicSharedMemorySize,
                         SMEM_BYTES);

    k_logpi<<<1, 512>>>(pi);
    k_prepA<<<NST, 512>>>(A);
    k_prepE<<<NST, 512>>>(E);
    hmm_main<<<NGRP * RANKS, THREADS, SMEM_BYTES>>>(x, T, out);
}